// round 5
// baseline (speedup 1.0000x reference)
#include <cuda_runtime.h>
#include <cuda_bf16.h>
#include <cstdint>

// TransposeTDLayer via warp-specialized bf16-split mma.sync GEMM.
// y[b,p,o] = bias[p,o] + sum_{(k,l):k+2l=p} sum_ci W[k,l,o,ci] * x[b,l,ci]
// Per p: D[128 x 64] = sum_j A_j[128x128] B_j[64x128]^T, both K-major.
// fp32 -> bf16 hi + residual lo; 3 MMAs hh,hl,lh.
// 8 consumer warps (MMA) + 4 producer warps (LDG+convert+STS), double buffer,
// named-barrier producer/consumer handoff.

#define BATCH 64
#define LIN   512
#define CIN   128
#define COUT  128
#define OUTP  1030

#define NTHREADS 384   // 256 consumers + 128 producers

// bf16 tile row stride: 128 bf16 + 8 pad = 136 el = 272 B
#define RSTRIDE 272
#define AHI_OFF 0
#define ALO_OFF 34816                 // 128*272
#define BHI_OFF 69632
#define BLO_OFF 87040                 // + 64*272
#define BUF_BYTES 104448
#define SMEM_TOTAL (2 * BUF_BYTES)    // 208896

// named barriers: FULL[s] = 1+s (producers arrive, consumers sync)
//                 EMPTY[s] = 3+s (consumers arrive, producers sync)
#define BAR_ARRIVE(id) asm volatile("bar.arrive %0, %1;" :: "r"(id), "r"(NTHREADS) : "memory")
#define BAR_SYNC(id)   asm volatile("bar.sync %0, %1;"   :: "r"(id), "r"(NTHREADS) : "memory")

static __device__ __forceinline__ uint32_t smem_u32(const void* p) {
    uint32_t a;
    asm("{ .reg .u64 t; cvta.to.shared.u64 t, %1; cvt.u32.u64 %0, t; }"
        : "=r"(a) : "l"(p));
    return a;
}

static __device__ __forceinline__ void mma_bf16(
    float* c, const uint32_t* a, const uint32_t* b)
{
    asm volatile(
        "mma.sync.aligned.m16n8k16.row.col.f32.bf16.bf16.f32 "
        "{%0,%1,%2,%3}, {%4,%5,%6,%7}, {%8,%9}, {%0,%1,%2,%3};"
        : "+f"(c[0]), "+f"(c[1]), "+f"(c[2]), "+f"(c[3])
        : "r"(a[0]), "r"(a[1]), "r"(a[2]), "r"(a[3]), "r"(b[0]), "r"(b[1]));
}

static __device__ __forceinline__ void ldsm_x4(uint32_t* r, uint32_t addr) {
    asm volatile("ldmatrix.sync.aligned.m8n8.x4.shared.b16 {%0,%1,%2,%3}, [%4];"
                 : "=r"(r[0]), "=r"(r[1]), "=r"(r[2]), "=r"(r[3]) : "r"(addr));
}

static __device__ __forceinline__ void split_store4(
    uint32_t hi_addr, uint32_t lo_addr, float4 v)
{
    __nv_bfloat162 h0 = __floats2bfloat162_rn(v.x, v.y);
    __nv_bfloat162 h1 = __floats2bfloat162_rn(v.z, v.w);
    float rx = v.x - __bfloat162float(h0.x);
    float ry = v.y - __bfloat162float(h0.y);
    float rz = v.z - __bfloat162float(h1.x);
    float rw = v.w - __bfloat162float(h1.y);
    __nv_bfloat162 l0 = __floats2bfloat162_rn(rx, ry);
    __nv_bfloat162 l1 = __floats2bfloat162_rn(rz, rw);
    uint32_t uh0 = *reinterpret_cast<uint32_t*>(&h0);
    uint32_t uh1 = *reinterpret_cast<uint32_t*>(&h1);
    uint32_t ul0 = *reinterpret_cast<uint32_t*>(&l0);
    uint32_t ul1 = *reinterpret_cast<uint32_t*>(&l1);
    asm volatile("st.shared.v2.b32 [%0], {%1,%2};" :: "r"(hi_addr), "r"(uh0), "r"(uh1));
    asm volatile("st.shared.v2.b32 [%0], {%1,%2};" :: "r"(lo_addr), "r"(ul0), "r"(ul1));
}

__global__ void __launch_bounds__(NTHREADS, 1)
tdconv_ws_kernel(const float* __restrict__ x,
                 const float* __restrict__ w,
                 const float* __restrict__ bias,
                 float* __restrict__ y)
{
    extern __shared__ char smem[];
    const uint32_t sbase = smem_u32(smem);

    const int p    = blockIdx.x;
    const int tid  = threadIdx.x;
    const int wid  = tid >> 5;
    const int lane = tid & 31;

    // contributing blocks: k = par + 2j, l = m - j, j in [j0, j1]
    const int par = p & 1;
    const int m   = (p - par) >> 1;
    int j0 = m - (LIN - 1); if (j0 < 0) j0 = 0;
    int j1 = m < 3 ? m : 3;
    const int nblk = j1 - j0 + 1;

    if (wid >= 8) {
        // ================= PRODUCER (warps 8..11) =================
        const int ptid = tid - 256;   // 0..127
        for (int i = 0; i < nblk; i++) {
            const int j = j0 + i;
            const int l = m - j;
            const int k = par + 2 * j;
            const float* __restrict__ wp = w + (size_t)(k * LIN + l) * (COUT * CIN);
            const float* __restrict__ xl = x + (size_t)l * CIN;

            if (i >= 2) BAR_SYNC(3 + (i & 1));   // wait EMPTY[i&1]
            const uint32_t buf = sbase + (uint32_t)(i & 1) * BUF_BYTES;

            // A tile: 128x128 fp32 = 4096 float4; 32 per producer thread
            #pragma unroll 8
            for (int it = 0; it < 32; it++) {
                int idx = ptid + it * 128;
                float4 v = reinterpret_cast<const float4*>(wp)[idx];
                uint32_t off = (uint32_t)(idx >> 5) * RSTRIDE + (uint32_t)(idx & 31) * 8;
                split_store4(buf + AHI_OFF + off, buf + ALO_OFF + off, v);
            }
            // B tile: 64x128 fp32 = 2048 float4; 16 per producer thread
            #pragma unroll 8
            for (int it = 0; it < 16; it++) {
                int idx = ptid + it * 128;
                int b   = idx >> 5;
                float4 v = *reinterpret_cast<const float4*>(
                    xl + (size_t)b * (LIN * CIN) + (size_t)(idx & 31) * 4);
                uint32_t off = (uint32_t)b * RSTRIDE + (uint32_t)(idx & 31) * 8;
                split_store4(buf + BHI_OFF + off, buf + BLO_OFF + off, v);
            }
            BAR_ARRIVE(1 + (i & 1));             // signal FULL[i&1]
        }
        return;
    }

    // ================= CONSUMER (warps 0..7) =================
    const int g    = lane >> 2;     // 0..7
    const int t    = lane & 3;      // 0..3
    const int lr   = lane & 7;
    const int grp  = lane >> 3;     // 0..3

    const int mrow = (wid >> 1) * 32;   // cout base (0,32,64,96)
    const int ncol = (wid & 1) * 32;    // batch base (0,32)

    // ldmatrix lane offsets within a tile (bytes)
    const uint32_t a_loff = (uint32_t)(mrow + lr + (grp & 1) * 8) * RSTRIDE
                          + (uint32_t)(grp >> 1) * 16;
    const uint32_t b_loff = (uint32_t)(ncol + lr + (grp >> 1) * 8) * RSTRIDE
                          + (uint32_t)(grp & 1) * 16;

    // accumulators init with bias (same across batch cols)
    float acc[2][4][4];
    #pragma unroll
    for (int mi = 0; mi < 2; mi++) {
        const float b_g  = bias[p * COUT + mrow + mi * 16 + g];
        const float b_g8 = bias[p * COUT + mrow + mi * 16 + g + 8];
        #pragma unroll
        for (int ni = 0; ni < 4; ni++) {
            acc[mi][ni][0] = b_g;  acc[mi][ni][1] = b_g;
            acc[mi][ni][2] = b_g8; acc[mi][ni][3] = b_g8;
        }
    }

    for (int i = 0; i < nblk; i++) {
        BAR_SYNC(1 + (i & 1));                   // wait FULL[i&1]

        const uint32_t buf = sbase + (uint32_t)(i & 1) * BUF_BYTES;
        const uint32_t ah_base = buf + AHI_OFF + a_loff;
        const uint32_t al_base = buf + ALO_OFF + a_loff;
        const uint32_t bh_base = buf + BHI_OFF + b_loff;
        const uint32_t bl_base = buf + BLO_OFF + b_loff;

        #pragma unroll 2
        for (int ks = 0; ks < 8; ks++) {
            const uint32_t koff = (uint32_t)ks * 32;
            uint32_t ahi[2][4], alo[2][4], bh[2][4], bl[2][4];
            #pragma unroll
            for (int mi = 0; mi < 2; mi++) {
                ldsm_x4(ahi[mi], ah_base + (uint32_t)mi * (16 * RSTRIDE) + koff);
                ldsm_x4(alo[mi], al_base + (uint32_t)mi * (16 * RSTRIDE) + koff);
            }
            #pragma unroll
            for (int pr = 0; pr < 2; pr++) {
                ldsm_x4(bh[pr], bh_base + (uint32_t)pr * (16 * RSTRIDE) + koff);
                ldsm_x4(bl[pr], bl_base + (uint32_t)pr * (16 * RSTRIDE) + koff);
            }
            #pragma unroll
            for (int mi = 0; mi < 2; mi++)
                #pragma unroll
                for (int ni = 0; ni < 4; ni++) {
                    const uint32_t* bhp = &bh[ni >> 1][(ni & 1) * 2];
                    const uint32_t* blp = &bl[ni >> 1][(ni & 1) * 2];
                    mma_bf16(acc[mi][ni], ahi[mi], bhp);
                    mma_bf16(acc[mi][ni], ahi[mi], blp);
                    mma_bf16(acc[mi][ni], alo[mi], bhp);
                }
        }

        if (i + 2 < nblk) BAR_ARRIVE(3 + (i & 1));   // signal EMPTY[i&1]
    }

    // ---- epilogue: D[o,b] -> y[b,p,o] ----
    #pragma unroll
    for (int mi = 0; mi < 2; mi++) {
        const int o0 = mrow + mi * 16 + g;
        const int o8 = o0 + 8;
        #pragma unroll
        for (int ni = 0; ni < 4; ni++) {
            const int b0 = ncol + ni * 8 + 2 * t;
            float* y0 = y + ((size_t)b0 * OUTP + p) * COUT;
            float* y1 = y0 + (size_t)OUTP * COUT;
            y0[o0] = acc[mi][ni][0];
            y1[o0] = acc[mi][ni][1];
            y0[o8] = acc[mi][ni][2];
            y1[o8] = acc[mi][ni][3];
        }
    }
}

extern "C" void kernel_launch(void* const* d_in, const int* in_sizes, int n_in,
                              void* d_out, int out_size)
{
    const float* x    = (const float*)d_in[0];  // (64,512,128)
    const float* w    = (const float*)d_in[1];  // (8,512,128,128)
    const float* bias = (const float*)d_in[2];  // (1030,128)
    float* y = (float*)d_out;                   // (64,1030,128)

    static bool configured = false;
    if (!configured) {
        cudaFuncSetAttribute(tdconv_ws_kernel,
                             cudaFuncAttributeMaxDynamicSharedMemorySize, SMEM_TOTAL);
        configured = true;
    }
    tdconv_ws_kernel<<<OUTP, NTHREADS, SMEM_TOTAL>>>(x, w, bias, y);
}

// round 6
// speedup vs baseline: 1.3881x; 1.3881x over previous
#include <cuda_runtime.h>
#include <cuda_bf16.h>
#include <cstdint>

// TransposeTDLayer via tf32 mma.sync + cp.async double-buffered pipeline.
// y[b,p,o] = bias[p,o] + sum_{(k,l):k+2l=p} sum_ci W[k,l,o,ci] * x[b,l,ci]
// Per p: D[128 x 64] = sum_j A_j[128x128] B_j[64x128]^T, both K-major fp32.
// SMEM holds raw fp32 tiles (cp.async); fragments via ldmatrix.b16 (16B rows =
// 4 fp32, lane l -> (row l>>2, col l&3) == tf32 fragment layout), then
// cvt.rna.tf32.f32, single mma.sync.m16n8k8.tf32 per tile.

#define BATCH 64
#define LIN   512
#define CIN   128
#define COUT  128
#define OUTP  1030

// fp32 tile row stride: 128 fp32 + 4 pad = 132 words = 528 B (132 % 32 == 4:
// 8-row ldmatrix groups hit distinct bank groups)
#define RSTRIDE 528
#define A_OFF   0
#define A_BYTES (128 * RSTRIDE)            // 67584
#define B_OFF   A_BYTES
#define B_BYTES (64 * RSTRIDE)             // 33792
#define BUF_BYTES (A_BYTES + B_BYTES)      // 101376
#define SMEM_TOTAL (2 * BUF_BYTES)         // 202752

static __device__ __forceinline__ uint32_t smem_u32(const void* p) {
    uint32_t a;
    asm("{ .reg .u64 t; cvta.to.shared.u64 t, %1; cvt.u32.u64 %0, t; }"
        : "=r"(a) : "l"(p));
    return a;
}

static __device__ __forceinline__ void mma_tf32(
    float* c, const uint32_t* a, const uint32_t* b)
{
    asm volatile(
        "mma.sync.aligned.m16n8k8.row.col.f32.tf32.tf32.f32 "
        "{%0,%1,%2,%3}, {%4,%5,%6,%7}, {%8,%9}, {%0,%1,%2,%3};"
        : "+f"(c[0]), "+f"(c[1]), "+f"(c[2]), "+f"(c[3])
        : "r"(a[0]), "r"(a[1]), "r"(a[2]), "r"(a[3]), "r"(b[0]), "r"(b[1]));
}

static __device__ __forceinline__ void ldsm_x4(uint32_t* r, uint32_t addr) {
    asm volatile("ldmatrix.sync.aligned.m8n8.x4.shared.b16 {%0,%1,%2,%3}, [%4];"
                 : "=r"(r[0]), "=r"(r[1]), "=r"(r[2]), "=r"(r[3]) : "r"(addr));
}

static __device__ __forceinline__ uint32_t cvt_tf32(uint32_t v) {
    uint32_t r;
    asm("cvt.rna.tf32.f32 %0, %1;" : "=r"(r) : "r"(v));
    return r;
}

static __device__ __forceinline__ void cpasync16(uint32_t dst, const void* src) {
    asm volatile("cp.async.cg.shared.global [%0], [%1], 16;"
                 :: "r"(dst), "l"(src) : "memory");
}
#define CP_COMMIT() asm volatile("cp.async.commit_group;" ::: "memory")
#define CP_WAIT1()  asm volatile("cp.async.wait_group 1;" ::: "memory")

__global__ void __launch_bounds__(256, 1)
tdconv_tf32_kernel(const float* __restrict__ x,
                   const float* __restrict__ w,
                   const float* __restrict__ bias,
                   float* __restrict__ y)
{
    extern __shared__ char smem[];
    const uint32_t sbase = smem_u32(smem);

    const int p    = blockIdx.x;
    const int tid  = threadIdx.x;
    const int wid  = tid >> 5;
    const int lane = tid & 31;
    const int g    = lane >> 2;     // 0..7
    const int t    = lane & 3;      // 0..3

    const int mrow = (wid >> 1) * 32;   // cout base (0,32,64,96)
    const int ncol = (wid & 1) * 32;    // batch base (0,32)

    // contributing blocks: k = par + 2j, l = m - j, j in [j0, j1]
    const int par = p & 1;
    const int m   = (p - par) >> 1;
    int j0 = m - (LIN - 1); if (j0 < 0) j0 = 0;
    int j1 = m < 3 ? m : 3;
    const int nblk = j1 - j0 + 1;

    // ---- producer lambda-ish: issue cp.async for block index i (if valid) ----
    // A: 128 rows x 32 chunks(16B); B: 64 rows x 32 chunks. 24 LDGSTS/thread.
    auto issue_block = [&](int i) {
        if (i < nblk) {
            const int j = j0 + i;
            const int l = m - j;
            const int k = par + 2 * j;
            const float* __restrict__ wp = w + (size_t)(k * LIN + l) * (COUT * CIN);
            const uint32_t buf = sbase + (uint32_t)(i & 1) * BUF_BYTES;
            #pragma unroll
            for (int it = 0; it < 16; it++) {
                int idx = tid + it * 256;
                int row = idx >> 5, c = idx & 31;
                cpasync16(buf + A_OFF + (uint32_t)row * RSTRIDE + (uint32_t)c * 16,
                          wp + (size_t)row * CIN + (size_t)c * 4);
            }
            #pragma unroll
            for (int it = 0; it < 8; it++) {
                int idx = tid + it * 256;
                int b = idx >> 5, c = idx & 31;
                cpasync16(buf + B_OFF + (uint32_t)b * RSTRIDE + (uint32_t)c * 16,
                          x + ((size_t)b * LIN + l) * CIN + (size_t)c * 4);
            }
        }
        CP_COMMIT();   // commit even when empty: uniform group counting
    };

    // ldmatrix lane byte-offsets (within tile, sans k-step / mi / pr terms)
    // A (per m16 tile): matrices (m0-7,k0-3),(m8-15,k0-3),(m0-7,k4-7),(m8-15,k4-7)
    const uint32_t a_loff = (uint32_t)(mrow + (lane & 7) + ((lane >> 3) & 1) * 8) * RSTRIDE
                          + (uint32_t)(lane >> 4) * 16;
    // B (per n16 pair): (n0-7,k0-3),(n0-7,k4-7),(n8-15,k0-3),(n8-15,k4-7)
    const uint32_t b_loff = (uint32_t)(ncol + (lane & 7) + (lane >> 4) * 8) * RSTRIDE
                          + (uint32_t)((lane >> 3) & 1) * 16;

    // accumulators init with bias (same across batch cols)
    float acc[2][4][4];
    #pragma unroll
    for (int mi = 0; mi < 2; mi++) {
        const float b_g  = bias[p * COUT + mrow + mi * 16 + g];
        const float b_g8 = bias[p * COUT + mrow + mi * 16 + g + 8];
        #pragma unroll
        for (int ni = 0; ni < 4; ni++) {
            acc[mi][ni][0] = b_g;  acc[mi][ni][1] = b_g;
            acc[mi][ni][2] = b_g8; acc[mi][ni][3] = b_g8;
        }
    }

    // ---- prologue: start blocks 0 and 1 ----
    issue_block(0);
    issue_block(1);

    for (int i = 0; i < nblk; i++) {
        CP_WAIT1();          // block i landed (allow block i+1 in flight)
        __syncthreads();

        const uint32_t buf = sbase + (uint32_t)(i & 1) * BUF_BYTES;
        const uint32_t ab = buf + A_OFF + a_loff;
        const uint32_t bb = buf + B_OFF + b_loff;

        #pragma unroll 4
        for (int ks = 0; ks < 16; ks++) {          // 16 k8-steps over K=128
            const uint32_t koff = (uint32_t)ks * 32;
            uint32_t a[2][4], b[2][4];
            #pragma unroll
            for (int mi = 0; mi < 2; mi++)
                ldsm_x4(a[mi], ab + (uint32_t)mi * (16 * RSTRIDE) + koff);
            #pragma unroll
            for (int pr = 0; pr < 2; pr++)
                ldsm_x4(b[pr], bb + (uint32_t)pr * (16 * RSTRIDE) + koff);

            #pragma unroll
            for (int mi = 0; mi < 2; mi++)
                #pragma unroll
                for (int q = 0; q < 4; q++) a[mi][q] = cvt_tf32(a[mi][q]);
            #pragma unroll
            for (int pr = 0; pr < 2; pr++)
                #pragma unroll
                for (int q = 0; q < 4; q++) b[pr][q] = cvt_tf32(b[pr][q]);

            #pragma unroll
            for (int mi = 0; mi < 2; mi++)
                #pragma unroll
                for (int ni = 0; ni < 4; ni++)
                    mma_tf32(acc[mi][ni], a[mi], &b[ni >> 1][(ni & 1) * 2]);
        }

        if (i + 2 < nblk) {
            __syncthreads();        // everyone done reading buf[i&1]
            issue_block(i + 2);     // refill it
        } else {
            CP_COMMIT();            // keep group count uniform for WAIT1
        }
    }

    // ---- epilogue: D[o,b] -> y[b,p,o] ----
    #pragma unroll
    for (int mi = 0; mi < 2; mi++) {
        const int o0 = mrow + mi * 16 + g;
        const int o8 = o0 + 8;
        #pragma unroll
        for (int ni = 0; ni < 4; ni++) {
            const int b0 = ncol + ni * 8 + 2 * t;
            float* y0 = y + ((size_t)b0 * OUTP + p) * COUT;
            float* y1 = y0 + (size_t)OUTP * COUT;
            y0[o0] = acc[mi][ni][0];
            y1[o0] = acc[mi][ni][1];
            y0[o8] = acc[mi][ni][2];
            y1[o8] = acc[mi][ni][3];
        }
    }
}

extern "C" void kernel_launch(void* const* d_in, const int* in_sizes, int n_in,
                              void* d_out, int out_size)
{
    const float* x    = (const float*)d_in[0];  // (64,512,128)
    const float* w    = (const float*)d_in[1];  // (8,512,128,128)
    const float* bias = (const float*)d_in[2];  // (1030,128)
    float* y = (float*)d_out;                   // (64,1030,128)

    static bool configured = false;
    if (!configured) {
        cudaFuncSetAttribute(tdconv_tf32_kernel,
                             cudaFuncAttributeMaxDynamicSharedMemorySize, SMEM_TOTAL);
        configured = true;
    }
    tdconv_tf32_kernel<<<OUTP, 256, SMEM_TOTAL>>>(x, w, bias, y);
}

// round 7
// speedup vs baseline: 1.7702x; 1.2752x over previous
#include <cuda_runtime.h>
#include <cuda_bf16.h>
#include <cstdint>

// TransposeTDLayer via tf32 mma.sync + cp.async, K=64-chunk double buffer,
// 2 CTAs/SM for latency hiding.
// y[b,p,o] = bias[p,o] + sum_{(k,l):k+2l=p} sum_ci W[k,l,o,ci] * x[b,l,ci]
// Per p: D[128 x 64] = sum_j A_j[128x128] B_j[64x128]^T, K-major fp32.
// Chunks: 2 per (k,l) block (K halves of 64). SMEM raw fp32; ldmatrix.b16
// yields tf32 fragment layout; cvt.rna.tf32.f32; mma.sync.m16n8k8.tf32.

#define BATCH 64
#define LIN   512
#define CIN   128
#define COUT  128
#define OUTP  1030

// chunk row stride: 64 fp32 + 4 pad = 68 words = 272 B (68 % 32 == 4)
#define RSTRIDE 272
#define A_OFF   0
#define A_BYTES (128 * RSTRIDE)            // 34816
#define B_OFF   A_BYTES
#define B_BYTES (64 * RSTRIDE)             // 17408
#define BUF_BYTES (A_BYTES + B_BYTES)      // 52224
#define SMEM_TOTAL (2 * BUF_BYTES)         // 104448

static __device__ __forceinline__ uint32_t smem_u32(const void* p) {
    uint32_t a;
    asm("{ .reg .u64 t; cvta.to.shared.u64 t, %1; cvt.u32.u64 %0, t; }"
        : "=r"(a) : "l"(p));
    return a;
}

static __device__ __forceinline__ void mma_tf32(
    float* c, const uint32_t* a, const uint32_t* b)
{
    asm volatile(
        "mma.sync.aligned.m16n8k8.row.col.f32.tf32.tf32.f32 "
        "{%0,%1,%2,%3}, {%4,%5,%6,%7}, {%8,%9}, {%0,%1,%2,%3};"
        : "+f"(c[0]), "+f"(c[1]), "+f"(c[2]), "+f"(c[3])
        : "r"(a[0]), "r"(a[1]), "r"(a[2]), "r"(a[3]), "r"(b[0]), "r"(b[1]));
}

static __device__ __forceinline__ void ldsm_x4(uint32_t* r, uint32_t addr) {
    asm volatile("ldmatrix.sync.aligned.m8n8.x4.shared.b16 {%0,%1,%2,%3}, [%4];"
                 : "=r"(r[0]), "=r"(r[1]), "=r"(r[2]), "=r"(r[3]) : "r"(addr));
}

static __device__ __forceinline__ uint32_t cvt_tf32(uint32_t v) {
    uint32_t r;
    asm("cvt.rna.tf32.f32 %0, %1;" : "=r"(r) : "r"(v));
    return r;
}

static __device__ __forceinline__ void cpasync16(uint32_t dst, const void* src) {
    asm volatile("cp.async.cg.shared.global [%0], [%1], 16;"
                 :: "r"(dst), "l"(src) : "memory");
}
#define CP_COMMIT() asm volatile("cp.async.commit_group;" ::: "memory")
#define CP_WAIT1()  asm volatile("cp.async.wait_group 1;" ::: "memory")

__global__ void __launch_bounds__(256, 2)
tdconv_tf32c_kernel(const float* __restrict__ x,
                    const float* __restrict__ w,
                    const float* __restrict__ bias,
                    float* __restrict__ y)
{
    extern __shared__ char smem[];
    const uint32_t sbase = smem_u32(smem);

    const int p    = blockIdx.x;
    const int tid  = threadIdx.x;
    const int wid  = tid >> 5;
    const int lane = tid & 31;
    const int g    = lane >> 2;
    const int t    = lane & 3;

    const int mrow = (wid >> 1) * 32;   // cout base (0,32,64,96)
    const int ncol = (wid & 1) * 32;    // batch base (0,32)

    // contributing blocks: k = par + 2j, l = m - j, j in [j0, j1]
    const int par = p & 1;
    const int m   = (p - par) >> 1;
    int j0 = m - (LIN - 1); if (j0 < 0) j0 = 0;
    int j1 = m < 3 ? m : 3;
    const int nblk    = j1 - j0 + 1;
    const int nchunks = 2 * nblk;       // K=64 halves

    // issue cp.async for chunk c (block c>>1, K-half c&1) into buf[c&1... no,
    // buf[c % 2] — double buffer over chunks
    auto issue_chunk = [&](int c) {
        if (c < nchunks) {
            const int j = j0 + (c >> 1);
            const int l = m - j;
            const int k = par + 2 * j;
            const int kh = (c & 1) * 64;    // K offset within block
            const float* __restrict__ wp =
                w + (size_t)(k * LIN + l) * (COUT * CIN) + kh;
            const float* __restrict__ xp = x + (size_t)l * CIN + kh;
            const uint32_t buf = sbase + (uint32_t)(c & 1) * BUF_BYTES;
            // A: 128 rows x 16 seg(16B) = 2048; 8 per thread
            #pragma unroll
            for (int it = 0; it < 8; it++) {
                int idx = tid + it * 256;
                int row = idx >> 4, cc = idx & 15;
                cpasync16(buf + A_OFF + (uint32_t)row * RSTRIDE + (uint32_t)cc * 16,
                          wp + (size_t)row * CIN + (size_t)cc * 4);
            }
            // B: 64 rows x 16 seg = 1024; 4 per thread
            #pragma unroll
            for (int it = 0; it < 4; it++) {
                int idx = tid + it * 256;
                int b = idx >> 4, cc = idx & 15;
                cpasync16(buf + B_OFF + (uint32_t)b * RSTRIDE + (uint32_t)cc * 16,
                          xp + (size_t)b * (LIN * CIN) + (size_t)cc * 4);
            }
        }
        CP_COMMIT();   // uniform group counting
    };

    // ldmatrix lane byte-offsets (within chunk)
    const uint32_t a_loff = (uint32_t)(mrow + (lane & 7) + ((lane >> 3) & 1) * 8) * RSTRIDE
                          + (uint32_t)(lane >> 4) * 16;
    const uint32_t b_loff = (uint32_t)(ncol + (lane & 7) + (lane >> 4) * 8) * RSTRIDE
                          + (uint32_t)((lane >> 3) & 1) * 16;

    // accumulators init with bias (same across batch cols)
    float acc[2][4][4];
    #pragma unroll
    for (int mi = 0; mi < 2; mi++) {
        const float b_g  = bias[p * COUT + mrow + mi * 16 + g];
        const float b_g8 = bias[p * COUT + mrow + mi * 16 + g + 8];
        #pragma unroll
        for (int ni = 0; ni < 4; ni++) {
            acc[mi][ni][0] = b_g;  acc[mi][ni][1] = b_g;
            acc[mi][ni][2] = b_g8; acc[mi][ni][3] = b_g8;
        }
    }

    issue_chunk(0);
    issue_chunk(1);

    for (int c = 0; c < nchunks; c++) {
        CP_WAIT1();
        __syncthreads();

        const uint32_t buf = sbase + (uint32_t)(c & 1) * BUF_BYTES;
        const uint32_t ab = buf + A_OFF + a_loff;
        const uint32_t bb = buf + B_OFF + b_loff;

        #pragma unroll 2
        for (int ks = 0; ks < 8; ks++) {           // 8 k8-steps over K=64
            const uint32_t koff = (uint32_t)ks * 32;
            uint32_t a[2][4], b[2][4];
            #pragma unroll
            for (int mi = 0; mi < 2; mi++)
                ldsm_x4(a[mi], ab + (uint32_t)mi * (16 * RSTRIDE) + koff);
            #pragma unroll
            for (int pr = 0; pr < 2; pr++)
                ldsm_x4(b[pr], bb + (uint32_t)pr * (16 * RSTRIDE) + koff);

            #pragma unroll
            for (int mi = 0; mi < 2; mi++)
                #pragma unroll
                for (int q = 0; q < 4; q++) a[mi][q] = cvt_tf32(a[mi][q]);
            #pragma unroll
            for (int pr = 0; pr < 2; pr++)
                #pragma unroll
                for (int q = 0; q < 4; q++) b[pr][q] = cvt_tf32(b[pr][q]);

            #pragma unroll
            for (int mi = 0; mi < 2; mi++)
                #pragma unroll
                for (int ni = 0; ni < 4; ni++)
                    mma_tf32(acc[mi][ni], a[mi], &b[ni >> 1][(ni & 1) * 2]);
        }

        __syncthreads();          // all warps done reading buf[c&1]
        issue_chunk(c + 2);       // refill it (commits even when exhausted)
    }

    // ---- epilogue: D[o,b] -> y[b,p,o] ----
    #pragma unroll
    for (int mi = 0; mi < 2; mi++) {
        const int o0 = mrow + mi * 16 + g;
        const int o8 = o0 + 8;
        #pragma unroll
        for (int ni = 0; ni < 4; ni++) {
            const int b0 = ncol + ni * 8 + 2 * t;
            float* y0 = y + ((size_t)b0 * OUTP + p) * COUT;
            float* y1 = y0 + (size_t)OUTP * COUT;
            y0[o0] = acc[mi][ni][0];
            y1[o0] = acc[mi][ni][1];
            y0[o8] = acc[mi][ni][2];
            y1[o8] = acc[mi][ni][3];
        }
    }
}

extern "C" void kernel_launch(void* const* d_in, const int* in_sizes, int n_in,
                              void* d_out, int out_size)
{
    const float* x    = (const float*)d_in[0];  // (64,512,128)
    const float* w    = (const float*)d_in[1];  // (8,512,128,128)
    const float* bias = (const float*)d_in[2];  // (1030,128)
    float* y = (float*)d_out;                   // (64,1030,128)

    static bool configured = false;
    if (!configured) {
        cudaFuncSetAttribute(tdconv_tf32c_kernel,
                             cudaFuncAttributeMaxDynamicSharedMemorySize, SMEM_TOTAL);
        configured = true;
    }
    tdconv_tf32c_kernel<<<OUTP, 256, SMEM_TOTAL>>>(x, w, bias, y);
}

// round 8
// speedup vs baseline: 1.9878x; 1.1229x over previous
#include <cuda_runtime.h>
#include <cuda_bf16.h>
#include <cstdint>

// TransposeTDLayer via tf32 mma.sync + cp.async, K=32-chunk double buffer,
// 3 CTAs/SM.
// y[b,p,o] = bias[p,o] + sum_{(k,l):k+2l=p} sum_ci W[k,l,o,ci] * x[b,l,ci]
// Per p: D[128 x 64] = sum_j A_j[128x128] B_j[64x128]^T, K-major fp32.
// Chunks: 4 per (k,l) block (K quarters of 32). SMEM raw fp32; ldmatrix.b16
// yields tf32 fragment layout; cvt.rna.tf32.f32; mma.sync.m16n8k8.tf32.

#define BATCH 64
#define LIN   512
#define CIN   128
#define COUT  128
#define OUTP  1030

// chunk row stride: 32 fp32 + 4 pad = 36 words = 144 B (36 % 32 == 4)
#define RSTRIDE 144
#define A_OFF   0
#define A_BYTES (128 * RSTRIDE)            // 18432
#define B_OFF   A_BYTES
#define B_BYTES (64 * RSTRIDE)             // 9216
#define BUF_BYTES (A_BYTES + B_BYTES)      // 27648
#define SMEM_TOTAL (2 * BUF_BYTES)         // 55296 per CTA -> 3 CTAs/SM

static __device__ __forceinline__ uint32_t smem_u32(const void* p) {
    uint32_t a;
    asm("{ .reg .u64 t; cvta.to.shared.u64 t, %1; cvt.u32.u64 %0, t; }"
        : "=r"(a) : "l"(p));
    return a;
}

static __device__ __forceinline__ void mma_tf32(
    float* c, const uint32_t* a, const uint32_t* b)
{
    asm volatile(
        "mma.sync.aligned.m16n8k8.row.col.f32.tf32.tf32.f32 "
        "{%0,%1,%2,%3}, {%4,%5,%6,%7}, {%8,%9}, {%0,%1,%2,%3};"
        : "+f"(c[0]), "+f"(c[1]), "+f"(c[2]), "+f"(c[3])
        : "r"(a[0]), "r"(a[1]), "r"(a[2]), "r"(a[3]), "r"(b[0]), "r"(b[1]));
}

static __device__ __forceinline__ void ldsm_x4(uint32_t* r, uint32_t addr) {
    asm volatile("ldmatrix.sync.aligned.m8n8.x4.shared.b16 {%0,%1,%2,%3}, [%4];"
                 : "=r"(r[0]), "=r"(r[1]), "=r"(r[2]), "=r"(r[3]) : "r"(addr));
}

static __device__ __forceinline__ uint32_t cvt_tf32(uint32_t v) {
    uint32_t r;
    asm("cvt.rna.tf32.f32 %0, %1;" : "=r"(r) : "r"(v));
    return r;
}

static __device__ __forceinline__ void cpasync16(uint32_t dst, const void* src) {
    asm volatile("cp.async.cg.shared.global [%0], [%1], 16;"
                 :: "r"(dst), "l"(src) : "memory");
}
#define CP_COMMIT() asm volatile("cp.async.commit_group;" ::: "memory")
#define CP_WAIT1()  asm volatile("cp.async.wait_group 1;" ::: "memory")

__global__ void __launch_bounds__(256, 3)
tdconv_tf32q_kernel(const float* __restrict__ x,
                    const float* __restrict__ w,
                    const float* __restrict__ bias,
                    float* __restrict__ y)
{
    extern __shared__ char smem[];
    const uint32_t sbase = smem_u32(smem);

    const int p    = blockIdx.x;
    const int tid  = threadIdx.x;
    const int wid  = tid >> 5;
    const int lane = tid & 31;

    const int mrow = (wid >> 1) * 32;   // cout base (0,32,64,96)
    const int ncol = (wid & 1) * 32;    // batch base (0,32)

    // contributing blocks: k = par + 2j, l = m - j, j in [j0, j1]
    const int par = p & 1;
    const int m   = (p - par) >> 1;
    int j0 = m - (LIN - 1); if (j0 < 0) j0 = 0;
    int j1 = m < 3 ? m : 3;
    const int nblk    = j1 - j0 + 1;
    const int nchunks = 4 * nblk;       // K=32 quarters

    // issue cp.async for chunk c (block c>>2, K-quarter c&3) into buf[c&1]
    auto issue_chunk = [&](int c) {
        if (c < nchunks) {
            const int j = j0 + (c >> 2);
            const int l = m - j;
            const int k = par + 2 * j;
            const int kh = (c & 3) * 32;
            const float* __restrict__ wp =
                w + (size_t)(k * LIN + l) * (COUT * CIN) + kh;
            const float* __restrict__ xp = x + (size_t)l * CIN + kh;
            const uint32_t buf = sbase + (uint32_t)(c & 1) * BUF_BYTES;
            // A: 128 rows x 8 seg(16B) = 1024; 4 per thread
            #pragma unroll
            for (int it = 0; it < 4; it++) {
                int idx = tid + it * 256;
                int row = idx >> 3, cc = idx & 7;
                cpasync16(buf + A_OFF + (uint32_t)row * RSTRIDE + (uint32_t)cc * 16,
                          wp + (size_t)row * CIN + (size_t)cc * 4);
            }
            // B: 64 rows x 8 seg = 512; 2 per thread
            #pragma unroll
            for (int it = 0; it < 2; it++) {
                int idx = tid + it * 256;
                int b = idx >> 3, cc = idx & 7;
                cpasync16(buf + B_OFF + (uint32_t)b * RSTRIDE + (uint32_t)cc * 16,
                          xp + (size_t)b * (LIN * CIN) + (size_t)cc * 4);
            }
        }
        CP_COMMIT();   // uniform group counting
    };

    // ldmatrix lane byte-offsets (within chunk)
    const uint32_t a_loff = (uint32_t)(mrow + (lane & 7) + ((lane >> 3) & 1) * 8) * RSTRIDE
                          + (uint32_t)(lane >> 4) * 16;
    const uint32_t b_loff = (uint32_t)(ncol + (lane & 7) + (lane >> 4) * 8) * RSTRIDE
                          + (uint32_t)((lane >> 3) & 1) * 16;

    // accumulators init with bias (same across batch cols)
    const int g = lane >> 2;
    float acc[2][4][4];
    #pragma unroll
    for (int mi = 0; mi < 2; mi++) {
        const float b_g  = bias[p * COUT + mrow + mi * 16 + g];
        const float b_g8 = bias[p * COUT + mrow + mi * 16 + g + 8];
        #pragma unroll
        for (int ni = 0; ni < 4; ni++) {
            acc[mi][ni][0] = b_g;  acc[mi][ni][1] = b_g;
            acc[mi][ni][2] = b_g8; acc[mi][ni][3] = b_g8;
        }
    }

    issue_chunk(0);
    issue_chunk(1);

    for (int c = 0; c < nchunks; c++) {
        CP_WAIT1();
        __syncthreads();

        const uint32_t buf = sbase + (uint32_t)(c & 1) * BUF_BYTES;
        const uint32_t ab = buf + A_OFF + a_loff;
        const uint32_t bb = buf + B_OFF + b_loff;

        #pragma unroll
        for (int ks = 0; ks < 4; ks++) {           // 4 k8-steps over K=32
            const uint32_t koff = (uint32_t)ks * 32;
            uint32_t a[2][4], b[2][4];
            #pragma unroll
            for (int mi = 0; mi < 2; mi++)
                ldsm_x4(a[mi], ab + (uint32_t)mi * (16 * RSTRIDE) + koff);
            #pragma unroll
            for (int pr = 0; pr < 2; pr++)
                ldsm_x4(b[pr], bb + (uint32_t)pr * (16 * RSTRIDE) + koff);

            #pragma unroll
            for (int mi = 0; mi < 2; mi++)
                #pragma unroll
                for (int q = 0; q < 4; q++) a[mi][q] = cvt_tf32(a[mi][q]);
            #pragma unroll
            for (int pr = 0; pr < 2; pr++)
                #pragma unroll
                for (int q = 0; q < 4; q++) b[pr][q] = cvt_tf32(b[pr][q]);

            #pragma unroll
            for (int mi = 0; mi < 2; mi++)
                #pragma unroll
                for (int ni = 0; ni < 4; ni++)
                    mma_tf32(acc[mi][ni], a[mi], &b[ni >> 1][(ni & 1) * 2]);
        }

        __syncthreads();          // all warps done reading buf[c&1]
        issue_chunk(c + 2);       // refill (commits even when exhausted)
    }

    // ---- epilogue: D[o,b] -> y[b,p,o] ----
    const int t = lane & 3;
    #pragma unroll
    for (int mi = 0; mi < 2; mi++) {
        const int o0 = mrow + mi * 16 + g;
        const int o8 = o0 + 8;
        #pragma unroll
        for (int ni = 0; ni < 4; ni++) {
            const int b0 = ncol + ni * 8 + 2 * t;
            float* y0 = y + ((size_t)b0 * OUTP + p) * COUT;
            float* y1 = y0 + (size_t)OUTP * COUT;
            y0[o0] = acc[mi][ni][0];
            y1[o0] = acc[mi][ni][1];
            y0[o8] = acc[mi][ni][2];
            y1[o8] = acc[mi][ni][3];
        }
    }
}

extern "C" void kernel_launch(void* const* d_in, const int* in_sizes, int n_in,
                              void* d_out, int out_size)
{
    const float* x    = (const float*)d_in[0];  // (64,512,128)
    const float* w    = (const float*)d_in[1];  // (8,512,128,128)
    const float* bias = (const float*)d_in[2];  // (1030,128)
    float* y = (float*)d_out;                   // (64,1030,128)

    static bool configured = false;
    if (!configured) {
        cudaFuncSetAttribute(tdconv_tf32q_kernel,
                             cudaFuncAttributeMaxDynamicSharedMemorySize, SMEM_TOTAL);
        configured = true;
    }
    tdconv_tf32q_kernel<<<OUTP, 256, SMEM_TOTAL>>>(x, w, bias, y);
}

// round 9
// speedup vs baseline: 2.1419x; 1.0775x over previous
#include <cuda_runtime.h>
#include <cuda_bf16.h>
#include <cstdint>

// TransposeTDLayer via tf32 mma.sync + cp.async, K=32-chunk double buffer,
// 4 CTAs/SM (64-reg cap).
// y[b,p,o] = bias[p,o] + sum_{(k,l):k+2l=p} sum_ci W[k,l,o,ci] * x[b,l,ci]
// Per p: D[128 x 64] = sum_j A_j[128x128] B_j[64x128]^T, K-major fp32.
// SMEM raw fp32; ldmatrix.b16 yields tf32 fragment layout; cvt.rna.tf32.f32;
// mma.sync.m16n8k8.tf32.

#define BATCH 64
#define LIN   512
#define CIN   128
#define COUT  128
#define OUTP  1030

// chunk row stride: 32 fp32 + 4 pad = 36 words = 144 B (36 % 32 == 4)
#define RSTRIDE 144
#define A_OFF   0
#define A_BYTES (128 * RSTRIDE)            // 18432
#define B_OFF   A_BYTES
#define B_BYTES (64 * RSTRIDE)             // 9216
#define BUF_BYTES (A_BYTES + B_BYTES)      // 27648
#define SMEM_TOTAL (2 * BUF_BYTES)         // 55296/CTA -> 4 CTAs = 221184 B

static __device__ __forceinline__ uint32_t smem_u32(const void* p) {
    uint32_t a;
    asm("{ .reg .u64 t; cvta.to.shared.u64 t, %1; cvt.u32.u64 %0, t; }"
        : "=r"(a) : "l"(p));
    return a;
}

static __device__ __forceinline__ void mma_tf32(
    float* c, const uint32_t* a, const uint32_t* b)
{
    asm volatile(
        "mma.sync.aligned.m16n8k8.row.col.f32.tf32.tf32.f32 "
        "{%0,%1,%2,%3}, {%4,%5,%6,%7}, {%8,%9}, {%0,%1,%2,%3};"
        : "+f"(c[0]), "+f"(c[1]), "+f"(c[2]), "+f"(c[3])
        : "r"(a[0]), "r"(a[1]), "r"(a[2]), "r"(a[3]), "r"(b[0]), "r"(b[1]));
}

static __device__ __forceinline__ void ldsm_x4(uint32_t* r, uint32_t addr) {
    asm volatile("ldmatrix.sync.aligned.m8n8.x4.shared.b16 {%0,%1,%2,%3}, [%4];"
                 : "=r"(r[0]), "=r"(r[1]), "=r"(r[2]), "=r"(r[3]) : "r"(addr));
}

static __device__ __forceinline__ uint32_t cvt_tf32(uint32_t v) {
    uint32_t r;
    asm("cvt.rna.tf32.f32 %0, %1;" : "=r"(r) : "r"(v));
    return r;
}

static __device__ __forceinline__ void cpasync16(uint32_t dst, const void* src) {
    asm volatile("cp.async.cg.shared.global [%0], [%1], 16;"
                 :: "r"(dst), "l"(src) : "memory");
}
#define CP_COMMIT() asm volatile("cp.async.commit_group;" ::: "memory")
#define CP_WAIT1()  asm volatile("cp.async.wait_group 1;" ::: "memory")

__global__ void __launch_bounds__(256, 4)
tdconv_tf32o4_kernel(const float* __restrict__ x,
                     const float* __restrict__ w,
                     const float* __restrict__ bias,
                     float* __restrict__ y)
{
    extern __shared__ char smem[];
    const uint32_t sbase = smem_u32(smem);

    const int p    = blockIdx.x;
    const int tid  = threadIdx.x;
    const int wid  = tid >> 5;
    const int lane = tid & 31;

    const int mrow = (wid >> 1) * 32;   // cout base (0,32,64,96)
    const int ncol = (wid & 1) * 32;    // batch base (0,32)

    // contributing blocks: k = par + 2j, l = m - j, j in [j0, j1]
    const int par = p & 1;
    const int m   = (p - par) >> 1;
    int j0 = m - (LIN - 1); if (j0 < 0) j0 = 0;
    int j1 = m < 3 ? m : 3;
    const int nblk    = j1 - j0 + 1;
    const int nchunks = 4 * nblk;       // K=32 quarters

    // hoisted per-thread cp.async decomposition
    const int a_row = tid >> 3;                 // 0..31 (A rows tid>>3 + 32*it)
    const int a_seg = (tid & 7) * 4;            // fp32 offset of 16B segment
    const uint32_t a_soff = (uint32_t)a_row * RSTRIDE + (uint32_t)(tid & 7) * 16;

    // issue cp.async for chunk c (block c>>2, K-quarter c&3) into buf[c&1]
    auto issue_chunk = [&](int c) {
        if (c < nchunks) {
            const int j = j0 + (c >> 2);
            const int l = m - j;
            const int k = par + 2 * j;
            const int kh = (c & 3) * 32;
            const float* __restrict__ wp =
                w + (size_t)(k * LIN + l) * (COUT * CIN) + kh + (size_t)a_row * CIN + a_seg;
            const float* __restrict__ xp =
                x + (size_t)l * CIN + kh + (size_t)a_row * (LIN * CIN) + a_seg;
            const uint32_t buf = sbase + (uint32_t)(c & 1) * BUF_BYTES;
            // A: rows a_row + 32*it
            #pragma unroll
            for (int it = 0; it < 4; it++)
                cpasync16(buf + A_OFF + a_soff + (uint32_t)it * (32 * RSTRIDE),
                          wp + (size_t)it * (32 * CIN));
            // B: rows a_row + 32*it (batch)
            #pragma unroll
            for (int it = 0; it < 2; it++)
                cpasync16(buf + B_OFF + a_soff + (uint32_t)it * (32 * RSTRIDE),
                          xp + (size_t)it * (32 * LIN * CIN));
        }
        CP_COMMIT();   // uniform group counting
    };

    // ldmatrix lane byte-offsets (within chunk)
    const uint32_t a_loff = A_OFF
        + (uint32_t)(mrow + (lane & 7) + ((lane >> 3) & 1) * 8) * RSTRIDE
        + (uint32_t)(lane >> 4) * 16;
    const uint32_t b_loff = B_OFF
        + (uint32_t)(ncol + (lane & 7) + (lane >> 4) * 8) * RSTRIDE
        + (uint32_t)((lane >> 3) & 1) * 16;

    // accumulators init with bias (same across batch cols)
    const int g = lane >> 2;
    float acc[2][4][4];
    #pragma unroll
    for (int mi = 0; mi < 2; mi++) {
        const float b_g  = bias[p * COUT + mrow + mi * 16 + g];
        const float b_g8 = bias[p * COUT + mrow + mi * 16 + g + 8];
        #pragma unroll
        for (int ni = 0; ni < 4; ni++) {
            acc[mi][ni][0] = b_g;  acc[mi][ni][1] = b_g;
            acc[mi][ni][2] = b_g8; acc[mi][ni][3] = b_g8;
        }
    }

    issue_chunk(0);
    issue_chunk(1);

    for (int c = 0; c < nchunks; c++) {
        CP_WAIT1();
        __syncthreads();

        const uint32_t buf = sbase + (uint32_t)(c & 1) * BUF_BYTES;
        const uint32_t ab = buf + a_loff;
        const uint32_t bb = buf + b_loff;

        #pragma unroll
        for (int ks = 0; ks < 4; ks++) {           // 4 k8-steps over K=32
            const uint32_t koff = (uint32_t)ks * 32;
            uint32_t a[2][4], b[2][4];
            #pragma unroll
            for (int mi = 0; mi < 2; mi++)
                ldsm_x4(a[mi], ab + (uint32_t)mi * (16 * RSTRIDE) + koff);
            #pragma unroll
            for (int pr = 0; pr < 2; pr++)
                ldsm_x4(b[pr], bb + (uint32_t)pr * (16 * RSTRIDE) + koff);

            #pragma unroll
            for (int mi = 0; mi < 2; mi++)
                #pragma unroll
                for (int q = 0; q < 4; q++) a[mi][q] = cvt_tf32(a[mi][q]);
            #pragma unroll
            for (int pr = 0; pr < 2; pr++)
                #pragma unroll
                for (int q = 0; q < 4; q++) b[pr][q] = cvt_tf32(b[pr][q]);

            #pragma unroll
            for (int mi = 0; mi < 2; mi++)
                #pragma unroll
                for (int ni = 0; ni < 4; ni++)
                    mma_tf32(acc[mi][ni], a[mi], &b[ni >> 1][(ni & 1) * 2]);
        }

        __syncthreads();          // all warps done reading buf[c&1]
        issue_chunk(c + 2);       // refill (commits even when exhausted)
    }

    // ---- epilogue: D[o,b] -> y[b,p,o] ----
    const int t = lane & 3;
    #pragma unroll
    for (int mi = 0; mi < 2; mi++) {
        const int o0 = mrow + mi * 16 + g;
        const int o8 = o0 + 8;
        #pragma unroll
        for (int ni = 0; ni < 4; ni++) {
            const int b0 = ncol + ni * 8 + 2 * t;
            float* y0 = y + ((size_t)b0 * OUTP + p) * COUT;
            float* y1 = y0 + (size_t)OUTP * COUT;
            y0[o0] = acc[mi][ni][0];
            y1[o0] = acc[mi][ni][1];
            y0[o8] = acc[mi][ni][2];
            y1[o8] = acc[mi][ni][3];
        }
    }
}

extern "C" void kernel_launch(void* const* d_in, const int* in_sizes, int n_in,
                              void* d_out, int out_size)
{
    const float* x    = (const float*)d_in[0];  // (64,512,128)
    const float* w    = (const float*)d_in[1];  // (8,512,128,128)
    const float* bias = (const float*)d_in[2];  // (1030,128)
    float* y = (float*)d_out;                   // (64,1030,128)

    static bool configured = false;
    if (!configured) {
        cudaFuncSetAttribute(tdconv_tf32o4_kernel,
                             cudaFuncAttributeMaxDynamicSharedMemorySize, SMEM_TOTAL);
        configured = true;
    }
    tdconv_tf32o4_kernel<<<OUTP, 256, SMEM_TOTAL>>>(x, w, bias, y);
}

// round 10
// speedup vs baseline: 2.1808x; 1.0182x over previous
#include <cuda_runtime.h>
#include <cuda_bf16.h>
#include <cstdint>

// TransposeTDLayer via tf32 mma.sync + cp.async, K=32-chunk double buffer,
// 4 CTAs/SM (64-reg cap).
// y[b,p,o] = bias[p,o] + sum_{(k,l):k+2l=p} sum_ci W[k,l,o,ci] * x[b,l,ci]
// Per p: D[128 x 64] = sum_j A_j[128x128] B_j[64x128]^T, K-major fp32.
// SMEM raw fp32; ldmatrix.b16 yields tf32 fragment layout.
// tf32 rounding via integer +0x1000 (== cvt.rna.tf32 for normal values,
// HMMA.TF32 truncates low 13 mantissa bits): IADD lat4 replaces F2F lat20.

#define BATCH 64
#define LIN   512
#define CIN   128
#define COUT  128
#define OUTP  1030

// chunk row stride: 32 fp32 + 4 pad = 36 words = 144 B (36 % 32 == 4)
#define RSTRIDE 144
#define A_OFF   0
#define A_BYTES (128 * RSTRIDE)            // 18432
#define B_OFF   A_BYTES
#define B_BYTES (64 * RSTRIDE)             // 9216
#define BUF_BYTES (A_BYTES + B_BYTES)      // 27648
#define SMEM_TOTAL (2 * BUF_BYTES)         // 55296/CTA -> 4 CTAs = 221184 B

static __device__ __forceinline__ uint32_t smem_u32(const void* p) {
    uint32_t a;
    asm("{ .reg .u64 t; cvta.to.shared.u64 t, %1; cvt.u32.u64 %0, t; }"
        : "=r"(a) : "l"(p));
    return a;
}

static __device__ __forceinline__ void mma_tf32(
    float* c, const uint32_t* a, const uint32_t* b)
{
    asm volatile(
        "mma.sync.aligned.m16n8k8.row.col.f32.tf32.tf32.f32 "
        "{%0,%1,%2,%3}, {%4,%5,%6,%7}, {%8,%9}, {%0,%1,%2,%3};"
        : "+f"(c[0]), "+f"(c[1]), "+f"(c[2]), "+f"(c[3])
        : "r"(a[0]), "r"(a[1]), "r"(a[2]), "r"(a[3]), "r"(b[0]), "r"(b[1]));
}

static __device__ __forceinline__ void ldsm_x4(uint32_t* r, uint32_t addr) {
    asm volatile("ldmatrix.sync.aligned.m8n8.x4.shared.b16 {%0,%1,%2,%3}, [%4];"
                 : "=r"(r[0]), "=r"(r[1]), "=r"(r[2]), "=r"(r[3]) : "r"(addr));
}

// tf32 round-to-nearest: add half-ulp of the 19-bit format; the tensor core
// truncates the low 13 mantissa bits. Bit-identical to cvt.rna.tf32.f32 for
// normal finite inputs, but runs on the fast ALU pipe (lat 4 vs ~20 for F2F).
static __device__ __forceinline__ uint32_t round_tf32(uint32_t v) {
    return v + 0x1000u;
}

static __device__ __forceinline__ void cpasync16(uint32_t dst, const void* src) {
    asm volatile("cp.async.cg.shared.global [%0], [%1], 16;"
                 :: "r"(dst), "l"(src) : "memory");
}
#define CP_COMMIT() asm volatile("cp.async.commit_group;" ::: "memory")
#define CP_WAIT1()  asm volatile("cp.async.wait_group 1;" ::: "memory")

__global__ void __launch_bounds__(256, 4)
tdconv_tf32r_kernel(const float* __restrict__ x,
                    const float* __restrict__ w,
                    const float* __restrict__ bias,
                    float* __restrict__ y)
{
    extern __shared__ char smem[];
    const uint32_t sbase = smem_u32(smem);

    const int p    = blockIdx.x;
    const int tid  = threadIdx.x;
    const int wid  = tid >> 5;
    const int lane = tid & 31;

    const int mrow = (wid >> 1) * 32;   // cout base (0,32,64,96)
    const int ncol = (wid & 1) * 32;    // batch base (0,32)

    // contributing blocks: k = par + 2j, l = m - j, j in [j0, j1]
    const int par = p & 1;
    const int m   = (p - par) >> 1;
    int j0 = m - (LIN - 1); if (j0 < 0) j0 = 0;
    int j1 = m < 3 ? m : 3;
    const int nblk    = j1 - j0 + 1;
    const int nchunks = 4 * nblk;       // K=32 quarters

    // hoisted per-thread cp.async decomposition
    const int a_row = tid >> 3;                 // 0..31
    const int a_seg = (tid & 7) * 4;            // fp32 offset of 16B segment
    const uint32_t a_soff = (uint32_t)a_row * RSTRIDE + (uint32_t)(tid & 7) * 16;

    // issue cp.async for chunk c (block c>>2, K-quarter c&3) into buf[c&1]
    auto issue_chunk = [&](int c) {
        if (c < nchunks) {
            const int j = j0 + (c >> 2);
            const int l = m - j;
            const int k = par + 2 * j;
            const int kh = (c & 3) * 32;
            const float* __restrict__ wp =
                w + (size_t)(k * LIN + l) * (COUT * CIN) + kh + (size_t)a_row * CIN + a_seg;
            const float* __restrict__ xp =
                x + (size_t)l * CIN + kh + (size_t)a_row * (LIN * CIN) + a_seg;
            const uint32_t buf = sbase + (uint32_t)(c & 1) * BUF_BYTES;
            #pragma unroll
            for (int it = 0; it < 4; it++)
                cpasync16(buf + A_OFF + a_soff + (uint32_t)it * (32 * RSTRIDE),
                          wp + (size_t)it * (32 * CIN));
            #pragma unroll
            for (int it = 0; it < 2; it++)
                cpasync16(buf + B_OFF + a_soff + (uint32_t)it * (32 * RSTRIDE),
                          xp + (size_t)it * (32 * LIN * CIN));
        }
        CP_COMMIT();   // uniform group counting
    };

    // ldmatrix lane byte-offsets (within chunk)
    const uint32_t a_loff = A_OFF
        + (uint32_t)(mrow + (lane & 7) + ((lane >> 3) & 1) * 8) * RSTRIDE
        + (uint32_t)(lane >> 4) * 16;
    const uint32_t b_loff = B_OFF
        + (uint32_t)(ncol + (lane & 7) + (lane >> 4) * 8) * RSTRIDE
        + (uint32_t)((lane >> 3) & 1) * 16;

    // accumulators init with bias (same across batch cols)
    const int g = lane >> 2;
    float acc[2][4][4];
    #pragma unroll
    for (int mi = 0; mi < 2; mi++) {
        const float b_g  = bias[p * COUT + mrow + mi * 16 + g];
        const float b_g8 = bias[p * COUT + mrow + mi * 16 + g + 8];
        #pragma unroll
        for (int ni = 0; ni < 4; ni++) {
            acc[mi][ni][0] = b_g;  acc[mi][ni][1] = b_g;
            acc[mi][ni][2] = b_g8; acc[mi][ni][3] = b_g8;
        }
    }

    issue_chunk(0);
    issue_chunk(1);

    for (int c = 0; c < nchunks; c++) {
        CP_WAIT1();
        __syncthreads();

        const uint32_t buf = sbase + (uint32_t)(c & 1) * BUF_BYTES;
        const uint32_t ab = buf + a_loff;
        const uint32_t bb = buf + b_loff;

        #pragma unroll
        for (int ks = 0; ks < 4; ks++) {           // 4 k8-steps over K=32
            const uint32_t koff = (uint32_t)ks * 32;
            uint32_t a[2][4], b[2][4];
            #pragma unroll
            for (int mi = 0; mi < 2; mi++)
                ldsm_x4(a[mi], ab + (uint32_t)mi * (16 * RSTRIDE) + koff);
            #pragma unroll
            for (int pr = 0; pr < 2; pr++)
                ldsm_x4(b[pr], bb + (uint32_t)pr * (16 * RSTRIDE) + koff);

            #pragma unroll
            for (int mi = 0; mi < 2; mi++)
                #pragma unroll
                for (int q = 0; q < 4; q++) a[mi][q] = round_tf32(a[mi][q]);
            #pragma unroll
            for (int pr = 0; pr < 2; pr++)
                #pragma unroll
                for (int q = 0; q < 4; q++) b[pr][q] = round_tf32(b[pr][q]);

            #pragma unroll
            for (int mi = 0; mi < 2; mi++)
                #pragma unroll
                for (int ni = 0; ni < 4; ni++)
                    mma_tf32(acc[mi][ni], a[mi], &b[ni >> 1][(ni & 1) * 2]);
        }

        __syncthreads();          // all warps done reading buf[c&1]
        issue_chunk(c + 2);       // refill (commits even when exhausted)
    }

    // ---- epilogue: D[o,b] -> y[b,p,o] ----
    const int t = lane & 3;
    #pragma unroll
    for (int mi = 0; mi < 2; mi++) {
        const int o0 = mrow + mi * 16 + g;
        const int o8 = o0 + 8;
        #pragma unroll
        for (int ni = 0; ni < 4; ni++) {
            const int b0 = ncol + ni * 8 + 2 * t;
            float* y0 = y + ((size_t)b0 * OUTP + p) * COUT;
            float* y1 = y0 + (size_t)OUTP * COUT;
            y0[o0] = acc[mi][ni][0];
            y1[o0] = acc[mi][ni][1];
            y0[o8] = acc[mi][ni][2];
            y1[o8] = acc[mi][ni][3];
        }
    }
}

extern "C" void kernel_launch(void* const* d_in, const int* in_sizes, int n_in,
                              void* d_out, int out_size)
{
    const float* x    = (const float*)d_in[0];  // (64,512,128)
    const float* w    = (const float*)d_in[1];  // (8,512,128,128)
    const float* bias = (const float*)d_in[2];  // (1030,128)
    float* y = (float*)d_out;                   // (64,1030,128)

    static bool configured = false;
    if (!configured) {
        cudaFuncSetAttribute(tdconv_tf32r_kernel,
                             cudaFuncAttributeMaxDynamicSharedMemorySize, SMEM_TOTAL);
        configured = true;
    }
    tdconv_tf32r_kernel<<<OUTP, 256, SMEM_TOTAL>>>(x, w, bias, y);
}